// round 1
// baseline (speedup 1.0000x reference)
#include <cuda_runtime.h>

#define NN 50000
#define NE 800000
#define NF 128
#define NH 64
#define NL 3
#define NG 512
#define NC 10

// Scratch (no allocations allowed)
__device__ float g_h[NN * NH];     // node features (post-layer)
__device__ float g_z[NN * NH];     // (1+eps)*h + aggregated neighbors
__device__ float g_t[NN * NH];     // MLP output pre-BN
__device__ float g_stats[2 * NH];  // column sums / sumsq
__device__ float g_pool[NG * NH];
__device__ float g_cnt[NG];

// ---------------------------------------------------------------------------
// Encoder: h = x @ enc_w + enc_b   ([NN,128] @ [128,64])
// Block = 256 thr (8 warps), each warp does 4 rows at a time, grid-stride.
// W staged in smem (32KB), row tiles in smem (16KB). Exactly 48KB static.
// ---------------------------------------------------------------------------
__global__ void enc_kernel(const float* __restrict__ x,
                           const float* __restrict__ w,
                           const float* __restrict__ b) {
    __shared__ float sW[NF * NH];        // 32768 B
    __shared__ float srow[8][4][NF];     // 16384 B
    int tid = threadIdx.x, wid = tid >> 5, lane = tid & 31;

    for (int i = tid; i < NF * NH / 4; i += 256)
        ((float4*)sW)[i] = ((const float4*)w)[i];
    float bias0 = __ldg(b + lane);
    float bias1 = __ldg(b + lane + 32);
    __syncthreads();

    for (int r0 = (blockIdx.x * 8 + wid) * 4; r0 < NN; r0 += gridDim.x * 32) {
#pragma unroll
        for (int j = 0; j < 4; j++) {
            float4 v = *(const float4*)(x + (size_t)(r0 + j) * NF + lane * 4);
            *(float4*)&srow[wid][j][lane * 4] = v;
        }
        __syncwarp();
        float a0[4], a1[4];
#pragma unroll
        for (int j = 0; j < 4; j++) { a0[j] = bias0; a1[j] = bias1; }
#pragma unroll 4
        for (int k = 0; k < NF; k++) {
            float w0 = sW[k * NH + lane];
            float w1v = sW[k * NH + lane + 32];
#pragma unroll
            for (int j = 0; j < 4; j++) {
                float zk = srow[wid][j][k];
                a0[j] += zk * w0;
                a1[j] += zk * w1v;
            }
        }
#pragma unroll
        for (int j = 0; j < 4; j++) {
            g_h[(size_t)(r0 + j) * NH + lane] = a0[j];
            g_h[(size_t)(r0 + j) * NH + lane + 32] = a1[j];
        }
        __syncwarp();
    }
}

// ---------------------------------------------------------------------------
// z = (1+eps[l]) * h ; also zero the BN stats accumulators
// ---------------------------------------------------------------------------
__global__ void init_kernel(const float* __restrict__ eps, int l) {
    int i = blockIdx.x * blockDim.x + threadIdx.x;
    float s = 1.0f + __ldg(eps + l);
    if (i < NN * NH / 4) {
        float4 v = ((const float4*)g_h)[i];
        v.x *= s; v.y *= s; v.z *= s; v.w *= s;
        ((float4*)g_z)[i] = v;
    }
    if (blockIdx.x == 0 && threadIdx.x < 2 * NH) g_stats[threadIdx.x] = 0.0f;
}

// ---------------------------------------------------------------------------
// Edge scatter: z[dst] += h[src]. 16 threads/edge, one v4 reduction each.
// h and z are L2-resident (12.8MB each).
// ---------------------------------------------------------------------------
__global__ void scatter_kernel(const int* __restrict__ ei) {
    int gid = blockIdx.x * blockDim.x + threadIdx.x;
    int e = gid >> 4;
    if (e >= NE) return;
    int q = (gid & 15) << 2;
    int s = __ldg(ei + e);
    int d = __ldg(ei + NE + e);
    float4 v = *(const float4*)(g_h + (size_t)s * NH + q);
    float* p = g_z + (size_t)d * NH + q;
    asm volatile("red.global.add.v4.f32 [%0], {%1,%2,%3,%4};"
                 :: "l"(p), "f"(v.x), "f"(v.y), "f"(v.z), "f"(v.w)
                 : "memory");
}

// ---------------------------------------------------------------------------
// Fused 2-layer MLP: t = relu(z@W1+b1); z2 = t@W2+b2 -> g_t
// Also accumulates per-column sum / sumsq for BN.
// ---------------------------------------------------------------------------
__global__ void mlp_kernel(const float* __restrict__ w1, const float* __restrict__ b1,
                           const float* __restrict__ w2, const float* __restrict__ b2) {
    __shared__ float sW1[NH * NH];   // 16KB
    __shared__ float sW2[NH * NH];   // 16KB
    __shared__ float srow[8][4][NH]; // 8KB
    __shared__ float ssum[NH], ssq[NH];
    int tid = threadIdx.x, wid = tid >> 5, lane = tid & 31;

    for (int i = tid; i < NH * NH / 4; i += 256) {
        ((float4*)sW1)[i] = ((const float4*)w1)[i];
        ((float4*)sW2)[i] = ((const float4*)w2)[i];
    }
    float b1l0 = __ldg(b1 + lane), b1l1 = __ldg(b1 + lane + 32);
    float b2l0 = __ldg(b2 + lane), b2l1 = __ldg(b2 + lane + 32);
    if (tid < NH) { ssum[tid] = 0.0f; ssq[tid] = 0.0f; }
    __syncthreads();

    float cs0 = 0.f, cq0 = 0.f, cs1 = 0.f, cq1 = 0.f;

    for (int r0 = (blockIdx.x * 8 + wid) * 4; r0 < NN; r0 += gridDim.x * 32) {
#pragma unroll
        for (int j = 0; j < 4; j++) {
            float2 v = *(const float2*)(g_z + (size_t)(r0 + j) * NH + lane * 2);
            srow[wid][j][lane * 2] = v.x;
            srow[wid][j][lane * 2 + 1] = v.y;
        }
        __syncwarp();
        float a0[4], a1[4];
#pragma unroll
        for (int j = 0; j < 4; j++) { a0[j] = b1l0; a1[j] = b1l1; }
#pragma unroll 4
        for (int k = 0; k < NH; k++) {
            float w0 = sW1[k * NH + lane];
            float w1v = sW1[k * NH + lane + 32];
#pragma unroll
            for (int j = 0; j < 4; j++) {
                float zk = srow[wid][j][k];
                a0[j] += zk * w0;
                a1[j] += zk * w1v;
            }
        }
        __syncwarp();
#pragma unroll
        for (int j = 0; j < 4; j++) {
            srow[wid][j][lane] = fmaxf(a0[j], 0.0f);
            srow[wid][j][lane + 32] = fmaxf(a1[j], 0.0f);
        }
        __syncwarp();
#pragma unroll
        for (int j = 0; j < 4; j++) { a0[j] = b2l0; a1[j] = b2l1; }
#pragma unroll 4
        for (int k = 0; k < NH; k++) {
            float w0 = sW2[k * NH + lane];
            float w1v = sW2[k * NH + lane + 32];
#pragma unroll
            for (int j = 0; j < 4; j++) {
                float zk = srow[wid][j][k];
                a0[j] += zk * w0;
                a1[j] += zk * w1v;
            }
        }
#pragma unroll
        for (int j = 0; j < 4; j++) {
            g_t[(size_t)(r0 + j) * NH + lane] = a0[j];
            g_t[(size_t)(r0 + j) * NH + lane + 32] = a1[j];
            cs0 += a0[j]; cq0 += a0[j] * a0[j];
            cs1 += a1[j]; cq1 += a1[j] * a1[j];
        }
        __syncwarp();
    }
    atomicAdd(&ssum[lane], cs0);
    atomicAdd(&ssum[lane + 32], cs1);
    atomicAdd(&ssq[lane], cq0);
    atomicAdd(&ssq[lane + 32], cq1);
    __syncthreads();
    if (tid < NH) {
        atomicAdd(&g_stats[tid], ssum[tid]);
        atomicAdd(&g_stats[NH + tid], ssq[tid]);
    }
}

// ---------------------------------------------------------------------------
// BN apply + ReLU: h = relu((t - mean) * rsqrt(var+eps) * gamma + beta)
// ---------------------------------------------------------------------------
__global__ void bn_kernel(const float* __restrict__ gamma,
                          const float* __restrict__ beta) {
    __shared__ float sc[NH], sh[NH];
    int tid = threadIdx.x;
    if (tid < NH) {
        float m = g_stats[tid] * (1.0f / NN);
        float v = g_stats[NH + tid] * (1.0f / NN) - m * m;
        float inv = rsqrtf(v + 1e-5f);
        float s = inv * __ldg(gamma + tid);
        sc[tid] = s;
        sh[tid] = __ldg(beta + tid) - m * s;
    }
    __syncthreads();
    for (int i = blockIdx.x * blockDim.x + tid; i < NN * NH / 4;
         i += gridDim.x * blockDim.x) {
        int c4 = (i & (NH / 4 - 1)) * 4;
        float4 v = ((const float4*)g_t)[i];
        v.x = fmaxf(v.x * sc[c4 + 0] + sh[c4 + 0], 0.0f);
        v.y = fmaxf(v.y * sc[c4 + 1] + sh[c4 + 1], 0.0f);
        v.z = fmaxf(v.z * sc[c4 + 2] + sh[c4 + 2], 0.0f);
        v.w = fmaxf(v.w * sc[c4 + 3] + sh[c4 + 3], 0.0f);
        ((float4*)g_h)[i] = v;
    }
}

// ---------------------------------------------------------------------------
// Pooling
// ---------------------------------------------------------------------------
__global__ void zeropool_kernel() {
    int i = blockIdx.x * blockDim.x + threadIdx.x;
    if (i < NG * NH) g_pool[i] = 0.0f;
    if (i < NG) g_cnt[i] = 0.0f;
}

__global__ void pool_kernel(const int* __restrict__ batch) {
    int gid = blockIdx.x * blockDim.x + threadIdx.x;
    int n = gid >> 4;
    if (n >= NN) return;
    int q = (gid & 15) << 2;
    int g = __ldg(batch + n);
    float4 v = *(const float4*)(g_h + (size_t)n * NH + q);
    float* p = g_pool + (size_t)g * NH + q;
    asm volatile("red.global.add.v4.f32 [%0], {%1,%2,%3,%4};"
                 :: "l"(p), "f"(v.x), "f"(v.y), "f"(v.z), "f"(v.w)
                 : "memory");
    if (q == 0) atomicAdd(&g_cnt[g], 1.0f);
}

__global__ void final_kernel(const float* __restrict__ lw,
                             const float* __restrict__ lb,
                             float* __restrict__ out) {
    __shared__ float sp[NH];
    int g = blockIdx.x, tid = threadIdx.x;
    float cnt = fmaxf(g_cnt[g], 1.0f);
    if (tid < NH) sp[tid] = g_pool[g * NH + tid] / cnt;
    __syncthreads();
    if (tid < NC) {
        float acc = __ldg(lb + tid);
        for (int k = 0; k < NH; k++) acc += sp[k] * __ldg(lw + k * NC + tid);
        out[g * NC + tid] = acc;
    }
}

// ---------------------------------------------------------------------------
extern "C" void kernel_launch(void* const* d_in, const int* in_sizes, int n_in,
                              void* d_out, int out_size) {
    const float* x     = (const float*)d_in[0];
    const int*   ei    = (const int*)d_in[1];
    const int*   batch = (const int*)d_in[2];
    const float* enc_w = (const float*)d_in[3];
    const float* enc_b = (const float*)d_in[4];
    const float* eps   = (const float*)d_in[5];
    const float* cw1   = (const float*)d_in[6];
    const float* cb1   = (const float*)d_in[7];
    const float* cw2   = (const float*)d_in[8];
    const float* cb2   = (const float*)d_in[9];
    const float* gam   = (const float*)d_in[10];
    const float* bet   = (const float*)d_in[11];
    const float* lw    = (const float*)d_in[12];
    const float* lb    = (const float*)d_in[13];
    float* out = (float*)d_out;

    enc_kernel<<<444, 256>>>(x, enc_w, enc_b);
    for (int l = 0; l < NL; l++) {
        init_kernel<<<(NN * NH / 4 + 255) / 256, 256>>>(eps, l);
        scatter_kernel<<<(NE * 16 + 255) / 256, 256>>>(ei);
        mlp_kernel<<<444, 256>>>(cw1 + (size_t)l * NH * NH, cb1 + l * NH,
                                 cw2 + (size_t)l * NH * NH, cb2 + l * NH);
        bn_kernel<<<444, 256>>>(gam + l * NH, bet + l * NH);
    }
    zeropool_kernel<<<(NG * NH + 255) / 256, 256>>>();
    pool_kernel<<<(NN * 16 + 255) / 256, 256>>>(batch);
    final_kernel<<<NG, 64>>>(lw, lb, out);
}

// round 2
// speedup vs baseline: 1.1150x; 1.1150x over previous
#include <cuda_runtime.h>

#define NN 50000
#define NE 800000
#define NF 128
#define NH 64
#define NL 3
#define NG 512
#define NC 10
#define SCAN_B 196   // ceil(50000/256)

// Scratch (no allocations allowed)
__device__ float g_h[NN * NH];
__device__ float g_z[NN * NH];
__device__ float g_t[NN * NH];
__device__ float g_stats[2 * NH];
__device__ float g_pool[NG * NH];
__device__ float g_cnt[NG];
// CSR scratch
__device__ int g_deg[NN];
__device__ int g_scan[SCAN_B * 256];
__device__ int g_bsum[SCAN_B];
__device__ int g_boff[SCAN_B];
__device__ int g_off[NN + 1];
__device__ int g_fill[NN];
__device__ int g_csr[NE];

// ---------------------------------------------------------------------------
// CSR build
// ---------------------------------------------------------------------------
__global__ void zero_deg_kernel() {
    int i = blockIdx.x * blockDim.x + threadIdx.x;
    if (i < NN) g_deg[i] = 0;
}

__global__ void hist_kernel(const int* __restrict__ ei) {
    int e = blockIdx.x * blockDim.x + threadIdx.x;
    if (e < NE) atomicAdd(&g_deg[__ldg(ei + NE + e)], 1);
}

__global__ void scan_block_kernel() {
    __shared__ int s[256];
    int tid = threadIdx.x, b = blockIdx.x, i = b * 256 + tid;
    int v = (i < NN) ? g_deg[i] : 0;
    s[tid] = v;
    __syncthreads();
#pragma unroll
    for (int d = 1; d < 256; d <<= 1) {
        int t = (tid >= d) ? s[tid - d] : 0;
        __syncthreads();
        s[tid] += t;
        __syncthreads();
    }
    g_scan[i] = s[tid];
    if (tid == 255) g_bsum[b] = s[255];
}

__global__ void scan_top_kernel() {
    __shared__ int s[256];
    int tid = threadIdx.x;
    int v = (tid < SCAN_B) ? g_bsum[tid] : 0;
    s[tid] = v;
    __syncthreads();
#pragma unroll
    for (int d = 1; d < 256; d <<= 1) {
        int t = (tid >= d) ? s[tid - d] : 0;
        __syncthreads();
        s[tid] += t;
        __syncthreads();
    }
    if (tid < SCAN_B) g_boff[tid] = s[tid] - v;  // exclusive block offsets
    if (tid == 0) g_off[NN] = NE;
}

__global__ void scan_apply_kernel() {
    int tid = threadIdx.x, b = blockIdx.x, i = b * 256 + tid;
    if (i < NN) {
        int e = g_boff[b] + g_scan[i] - g_deg[i];  // exclusive scan
        g_off[i] = e;
        g_fill[i] = e;
    }
}

__global__ void fill_kernel(const int* __restrict__ ei) {
    int e = blockIdx.x * blockDim.x + threadIdx.x;
    if (e >= NE) return;
    int s = __ldg(ei + e);
    int d = __ldg(ei + NE + e);
    int pos = atomicAdd(&g_fill[d], 1);
    g_csr[pos] = s;
}

// ---------------------------------------------------------------------------
// Encoder: h = x @ enc_w + enc_b  ([NN,128]@[128,64]), transposed-W smem,
// LDS.128 weight loads. 2 rows per warp. Static smem ~42KB.
// ---------------------------------------------------------------------------
__global__ void enc_kernel(const float* __restrict__ x,
                           const float* __restrict__ w,
                           const float* __restrict__ b) {
    __shared__ __align__(16) float sWt[NH * 132];      // [col][k], pad 132
    __shared__ __align__(16) float srow[8][2][NF];
    int tid = threadIdx.x, wid = tid >> 5, lane = tid & 31;

    for (int i = tid; i < NF * NH; i += 256) {
        int k = i >> 6, col = i & 63;
        sWt[col * 132 + k] = w[i];
    }
    float bias0 = __ldg(b + lane);
    float bias1 = __ldg(b + lane + 32);
    __syncthreads();

    for (int r0 = (blockIdx.x * 8 + wid) * 2; r0 < NN; r0 += gridDim.x * 16) {
#pragma unroll
        for (int j = 0; j < 2; j++)
            *(float4*)&srow[wid][j][lane * 4] =
                *(const float4*)(x + (size_t)(r0 + j) * NF + lane * 4);
        __syncwarp();
        float a0[2] = {bias0, bias0}, a1[2] = {bias1, bias1};
#pragma unroll
        for (int kb = 0; kb < NF / 4; kb++) {
            float4 wa = *(const float4*)&sWt[lane * 132 + kb * 4];
            float4 wb = *(const float4*)&sWt[(lane + 32) * 132 + kb * 4];
#pragma unroll
            for (int j = 0; j < 2; j++) {
                float4 z4 = *(const float4*)&srow[wid][j][kb * 4];
                a0[j] = fmaf(z4.x, wa.x, a0[j]);
                a0[j] = fmaf(z4.y, wa.y, a0[j]);
                a0[j] = fmaf(z4.z, wa.z, a0[j]);
                a0[j] = fmaf(z4.w, wa.w, a0[j]);
                a1[j] = fmaf(z4.x, wb.x, a1[j]);
                a1[j] = fmaf(z4.y, wb.y, a1[j]);
                a1[j] = fmaf(z4.z, wb.z, a1[j]);
                a1[j] = fmaf(z4.w, wb.w, a1[j]);
            }
        }
#pragma unroll
        for (int j = 0; j < 2; j++) {
            g_h[(size_t)(r0 + j) * NH + lane] = a0[j];
            g_h[(size_t)(r0 + j) * NH + lane + 32] = a1[j];
        }
        __syncwarp();
    }
}

// ---------------------------------------------------------------------------
// Gather: z = (1+eps)*h + sum_{src in CSR[dst]} h[src].  16 lanes per node.
// Also zeroes BN stats.
// ---------------------------------------------------------------------------
__global__ void gather_kernel(const float* __restrict__ eps, int l) {
    if (blockIdx.x == 0 && threadIdx.x < 2 * NH) g_stats[threadIdx.x] = 0.0f;
    int gid = blockIdx.x * blockDim.x + threadIdx.x;
    int node = gid >> 4;
    if (node >= NN) return;
    int lane16 = threadIdx.x & 15;
    unsigned hmask = 0xFFFFu << (threadIdx.x & 16);
    float se = 1.0f + __ldg(eps + l);

    float4 acc = *(const float4*)(g_h + (size_t)node * NH + lane16 * 4);
    acc.x *= se; acc.y *= se; acc.z *= se; acc.w *= se;

    int begin = __ldg(&g_off[node]);
    int end   = __ldg(&g_off[node + 1]);
    for (int base = begin; base < end; base += 16) {
        int cnt = min(16, end - base);
        int sidx = (lane16 < cnt) ? __ldg(&g_csr[base + lane16]) : 0;
        int j = 0;
        for (; j + 4 <= cnt; j += 4) {
            int s0 = __shfl_sync(hmask, sidx, j + 0, 16);
            int s1 = __shfl_sync(hmask, sidx, j + 1, 16);
            int s2 = __shfl_sync(hmask, sidx, j + 2, 16);
            int s3 = __shfl_sync(hmask, sidx, j + 3, 16);
            float4 v0 = *(const float4*)(g_h + (size_t)s0 * NH + lane16 * 4);
            float4 v1 = *(const float4*)(g_h + (size_t)s1 * NH + lane16 * 4);
            float4 v2 = *(const float4*)(g_h + (size_t)s2 * NH + lane16 * 4);
            float4 v3 = *(const float4*)(g_h + (size_t)s3 * NH + lane16 * 4);
            acc.x += v0.x; acc.y += v0.y; acc.z += v0.z; acc.w += v0.w;
            acc.x += v1.x; acc.y += v1.y; acc.z += v1.z; acc.w += v1.w;
            acc.x += v2.x; acc.y += v2.y; acc.z += v2.z; acc.w += v2.w;
            acc.x += v3.x; acc.y += v3.y; acc.z += v3.z; acc.w += v3.w;
        }
        for (; j < cnt; j++) {
            int s0 = __shfl_sync(hmask, sidx, j, 16);
            float4 v0 = *(const float4*)(g_h + (size_t)s0 * NH + lane16 * 4);
            acc.x += v0.x; acc.y += v0.y; acc.z += v0.z; acc.w += v0.w;
        }
    }
    *(float4*)(g_z + (size_t)node * NH + lane16 * 4) = acc;
}

// ---------------------------------------------------------------------------
// Fused 2-layer MLP with transposed weights (pad 68), LDS.128, 4 rows/warp.
// Accumulates BN stats. Static smem ~43.5KB.
// ---------------------------------------------------------------------------
__global__ void mlp_kernel(const float* __restrict__ w1, const float* __restrict__ b1,
                           const float* __restrict__ w2, const float* __restrict__ b2) {
    __shared__ __align__(16) float sW1t[NH * 68];
    __shared__ __align__(16) float sW2t[NH * 68];
    __shared__ __align__(16) float srow[8][4][NH];
    __shared__ float ssum[NH], ssq[NH];
    int tid = threadIdx.x, wid = tid >> 5, lane = tid & 31;

    for (int i = tid; i < NH * NH; i += 256) {
        int k = i >> 6, col = i & 63;
        sW1t[col * 68 + k] = w1[i];
        sW2t[col * 68 + k] = w2[i];
    }
    float b1l0 = __ldg(b1 + lane), b1l1 = __ldg(b1 + lane + 32);
    float b2l0 = __ldg(b2 + lane), b2l1 = __ldg(b2 + lane + 32);
    if (tid < NH) { ssum[tid] = 0.0f; ssq[tid] = 0.0f; }
    __syncthreads();

    float cs0 = 0.f, cq0 = 0.f, cs1 = 0.f, cq1 = 0.f;

    for (int r0 = (blockIdx.x * 8 + wid) * 4; r0 < NN; r0 += gridDim.x * 32) {
#pragma unroll
        for (int j = 0; j < 4; j++) {
            float2 v = *(const float2*)(g_z + (size_t)(r0 + j) * NH + lane * 2);
            srow[wid][j][lane * 2] = v.x;
            srow[wid][j][lane * 2 + 1] = v.y;
        }
        __syncwarp();
        float a0[4], a1[4];
#pragma unroll
        for (int j = 0; j < 4; j++) { a0[j] = b1l0; a1[j] = b1l1; }
#pragma unroll
        for (int kb = 0; kb < NH / 4; kb++) {
            float4 wa = *(const float4*)&sW1t[lane * 68 + kb * 4];
            float4 wb = *(const float4*)&sW1t[(lane + 32) * 68 + kb * 4];
#pragma unroll
            for (int j = 0; j < 4; j++) {
                float4 z4 = *(const float4*)&srow[wid][j][kb * 4];
                a0[j] = fmaf(z4.x, wa.x, a0[j]);
                a0[j] = fmaf(z4.y, wa.y, a0[j]);
                a0[j] = fmaf(z4.z, wa.z, a0[j]);
                a0[j] = fmaf(z4.w, wa.w, a0[j]);
                a1[j] = fmaf(z4.x, wb.x, a1[j]);
                a1[j] = fmaf(z4.y, wb.y, a1[j]);
                a1[j] = fmaf(z4.z, wb.z, a1[j]);
                a1[j] = fmaf(z4.w, wb.w, a1[j]);
            }
        }
        __syncwarp();
#pragma unroll
        for (int j = 0; j < 4; j++) {
            srow[wid][j][lane] = fmaxf(a0[j], 0.0f);
            srow[wid][j][lane + 32] = fmaxf(a1[j], 0.0f);
        }
        __syncwarp();
#pragma unroll
        for (int j = 0; j < 4; j++) { a0[j] = b2l0; a1[j] = b2l1; }
#pragma unroll
        for (int kb = 0; kb < NH / 4; kb++) {
            float4 wa = *(const float4*)&sW2t[lane * 68 + kb * 4];
            float4 wb = *(const float4*)&sW2t[(lane + 32) * 68 + kb * 4];
#pragma unroll
            for (int j = 0; j < 4; j++) {
                float4 z4 = *(const float4*)&srow[wid][j][kb * 4];
                a0[j] = fmaf(z4.x, wa.x, a0[j]);
                a0[j] = fmaf(z4.y, wa.y, a0[j]);
                a0[j] = fmaf(z4.z, wa.z, a0[j]);
                a0[j] = fmaf(z4.w, wa.w, a0[j]);
                a1[j] = fmaf(z4.x, wb.x, a1[j]);
                a1[j] = fmaf(z4.y, wb.y, a1[j]);
                a1[j] = fmaf(z4.z, wb.z, a1[j]);
                a1[j] = fmaf(z4.w, wb.w, a1[j]);
            }
        }
#pragma unroll
        for (int j = 0; j < 4; j++) {
            g_t[(size_t)(r0 + j) * NH + lane] = a0[j];
            g_t[(size_t)(r0 + j) * NH + lane + 32] = a1[j];
            cs0 += a0[j]; cq0 += a0[j] * a0[j];
            cs1 += a1[j]; cq1 += a1[j] * a1[j];
        }
        __syncwarp();
    }
    atomicAdd(&ssum[lane], cs0);
    atomicAdd(&ssum[lane + 32], cs1);
    atomicAdd(&ssq[lane], cq0);
    atomicAdd(&ssq[lane + 32], cq1);
    __syncthreads();
    if (tid < NH) {
        atomicAdd(&g_stats[tid], ssum[tid]);
        atomicAdd(&g_stats[NH + tid], ssq[tid]);
    }
}

// ---------------------------------------------------------------------------
// BN apply + ReLU
// ---------------------------------------------------------------------------
__global__ void bn_kernel(const float* __restrict__ gamma,
                          const float* __restrict__ beta) {
    __shared__ float sc[NH], sh[NH];
    int tid = threadIdx.x;
    if (tid < NH) {
        float m = g_stats[tid] * (1.0f / NN);
        float v = g_stats[NH + tid] * (1.0f / NN) - m * m;
        float inv = rsqrtf(v + 1e-5f);
        float s = inv * __ldg(gamma + tid);
        sc[tid] = s;
        sh[tid] = __ldg(beta + tid) - m * s;
    }
    __syncthreads();
    for (int i = blockIdx.x * blockDim.x + tid; i < NN * NH / 4;
         i += gridDim.x * blockDim.x) {
        int c4 = (i & (NH / 4 - 1)) * 4;
        float4 v = ((const float4*)g_t)[i];
        v.x = fmaxf(v.x * sc[c4 + 0] + sh[c4 + 0], 0.0f);
        v.y = fmaxf(v.y * sc[c4 + 1] + sh[c4 + 1], 0.0f);
        v.z = fmaxf(v.z * sc[c4 + 2] + sh[c4 + 2], 0.0f);
        v.w = fmaxf(v.w * sc[c4 + 3] + sh[c4 + 3], 0.0f);
        ((float4*)g_h)[i] = v;
    }
}

// ---------------------------------------------------------------------------
// Pooling + classifier
// ---------------------------------------------------------------------------
__global__ void zeropool_kernel() {
    int i = blockIdx.x * blockDim.x + threadIdx.x;
    if (i < NG * NH) g_pool[i] = 0.0f;
    if (i < NG) g_cnt[i] = 0.0f;
}

__global__ void pool_kernel(const int* __restrict__ batch) {
    int gid = blockIdx.x * blockDim.x + threadIdx.x;
    int n = gid >> 4;
    if (n >= NN) return;
    int q = (gid & 15) << 2;
    int g = __ldg(batch + n);
    float4 v = *(const float4*)(g_h + (size_t)n * NH + q);
    float* p = g_pool + (size_t)g * NH + q;
    asm volatile("red.global.add.v4.f32 [%0], {%1,%2,%3,%4};"
                 :: "l"(p), "f"(v.x), "f"(v.y), "f"(v.z), "f"(v.w)
                 : "memory");
    if (q == 0) atomicAdd(&g_cnt[g], 1.0f);
}

__global__ void final_kernel(const float* __restrict__ lw,
                             const float* __restrict__ lb,
                             float* __restrict__ out) {
    __shared__ float sp[NH];
    int g = blockIdx.x, tid = threadIdx.x;
    float cnt = fmaxf(g_cnt[g], 1.0f);
    if (tid < NH) sp[tid] = g_pool[g * NH + tid] / cnt;
    __syncthreads();
    if (tid < NC) {
        float acc = __ldg(lb + tid);
        for (int k = 0; k < NH; k++) acc += sp[k] * __ldg(lw + k * NC + tid);
        out[g * NC + tid] = acc;
    }
}

// ---------------------------------------------------------------------------
extern "C" void kernel_launch(void* const* d_in, const int* in_sizes, int n_in,
                              void* d_out, int out_size) {
    const float* x     = (const float*)d_in[0];
    const int*   ei    = (const int*)d_in[1];
    const int*   batch = (const int*)d_in[2];
    const float* enc_w = (const float*)d_in[3];
    const float* enc_b = (const float*)d_in[4];
    const float* eps   = (const float*)d_in[5];
    const float* cw1   = (const float*)d_in[6];
    const float* cb1   = (const float*)d_in[7];
    const float* cw2   = (const float*)d_in[8];
    const float* cb2   = (const float*)d_in[9];
    const float* gam   = (const float*)d_in[10];
    const float* bet   = (const float*)d_in[11];
    const float* lw    = (const float*)d_in[12];
    const float* lb    = (const float*)d_in[13];
    float* out = (float*)d_out;

    // CSR build (per launch; deterministic structure)
    zero_deg_kernel<<<SCAN_B, 256>>>();
    hist_kernel<<<(NE + 255) / 256, 256>>>(ei);
    scan_block_kernel<<<SCAN_B, 256>>>();
    scan_top_kernel<<<1, 256>>>();
    scan_apply_kernel<<<SCAN_B, 256>>>();
    fill_kernel<<<(NE + 255) / 256, 256>>>(ei);

    enc_kernel<<<444, 256>>>(x, enc_w, enc_b);
    for (int l = 0; l < NL; l++) {
        gather_kernel<<<(NN * 16 + 255) / 256, 256>>>(eps, l);
        mlp_kernel<<<444, 256>>>(cw1 + (size_t)l * NH * NH, cb1 + l * NH,
                                 cw2 + (size_t)l * NH * NH, cb2 + l * NH);
        bn_kernel<<<444, 256>>>(gam + l * NH, bet + l * NH);
    }
    zeropool_kernel<<<(NG * NH + 255) / 256, 256>>>();
    pool_kernel<<<(NN * 16 + 255) / 256, 256>>>(batch);
    final_kernel<<<NG, 64>>>(lw, lb, out);
}

// round 3
// speedup vs baseline: 1.2565x; 1.1269x over previous
#include <cuda_runtime.h>

#define NN 50000
#define NE 800000
#define NF 128
#define NH 64
#define NL 3
#define NG 512
#define NC 10
#define SCAN_B 196   // ceil(50000/256)

// Scratch (no allocations allowed)
__device__ float g_h[NN * NH];
__device__ float g_t[NN * NH];
__device__ float g_stats[NL][2 * NH];
__device__ float g_pool[NG * NH];
__device__ float g_cnt[NG];
// CSR scratch
__device__ int g_deg[NN];
__device__ int g_scan[SCAN_B * 256];
__device__ int g_bsum[SCAN_B];
__device__ int g_boff[SCAN_B];
__device__ int g_off[NN + 1];
__device__ int g_fill[NN];
__device__ int g_csr[NE];

// ---------------------------------------------------------------------------
// Zero everything that needs zeroing (deg, stats, pool, cnt) in one kernel.
// ---------------------------------------------------------------------------
__global__ void zero_misc_kernel() {
    int i = blockIdx.x * blockDim.x + threadIdx.x;
    if (i < NN) g_deg[i] = 0;
    if (i < NL * 2 * NH) ((float*)g_stats)[i] = 0.0f;
    if (i < NG * NH) g_pool[i] = 0.0f;
    if (i < NG) g_cnt[i] = 0.0f;
}

__global__ void hist_kernel(const int* __restrict__ ei) {
    int e = blockIdx.x * blockDim.x + threadIdx.x;
    if (e < NE) atomicAdd(&g_deg[__ldg(ei + NE + e)], 1);
}

__global__ void scan_block_kernel() {
    __shared__ int s[256];
    int tid = threadIdx.x, b = blockIdx.x, i = b * 256 + tid;
    int v = (i < NN) ? g_deg[i] : 0;
    s[tid] = v;
    __syncthreads();
#pragma unroll
    for (int d = 1; d < 256; d <<= 1) {
        int t = (tid >= d) ? s[tid - d] : 0;
        __syncthreads();
        s[tid] += t;
        __syncthreads();
    }
    g_scan[i] = s[tid];
    if (tid == 255) g_bsum[b] = s[255];
}

__global__ void scan_top_kernel() {
    __shared__ int s[256];
    int tid = threadIdx.x;
    int v = (tid < SCAN_B) ? g_bsum[tid] : 0;
    s[tid] = v;
    __syncthreads();
#pragma unroll
    for (int d = 1; d < 256; d <<= 1) {
        int t = (tid >= d) ? s[tid - d] : 0;
        __syncthreads();
        s[tid] += t;
        __syncthreads();
    }
    if (tid < SCAN_B) g_boff[tid] = s[tid] - v;
    if (tid == 0) g_off[NN] = NE;
}

__global__ void scan_apply_kernel() {
    int tid = threadIdx.x, b = blockIdx.x, i = b * 256 + tid;
    if (i < NN) {
        int e = g_boff[b] + g_scan[i] - g_deg[i];
        g_off[i] = e;
        g_fill[i] = e;
    }
}

__global__ void fill_kernel(const int* __restrict__ ei) {
    int e = blockIdx.x * blockDim.x + threadIdx.x;
    if (e >= NE) return;
    int s = __ldg(ei + e);
    int d = __ldg(ei + NE + e);
    int pos = atomicAdd(&g_fill[d], 1);
    g_csr[pos] = s;
}

// ---------------------------------------------------------------------------
// Encoder: h = x @ enc_w + enc_b  ([NN,128]@[128,64]).
// Weights in smem layout [half][kb][col][4] (conflict-free LDS.128, no pad).
// 4 rows per warp, x staged in 64-col halves. smem = 40KB.
// ---------------------------------------------------------------------------
__global__ void enc_kernel(const float* __restrict__ x,
                           const float* __restrict__ w,
                           const float* __restrict__ b) {
    __shared__ __align__(16) float sWt[2][16 * 256];  // 32KB
    __shared__ __align__(16) float srow[8][4][NH];    // 8KB
    int tid = threadIdx.x, wid = tid >> 5, lane = tid & 31;

    for (int i = tid; i < NF * NH; i += 256) {
        int k = i >> 6, col = i & 63;
        sWt[k >> 6][((k & 63) >> 2) * 256 + col * 4 + (k & 3)] = w[i];
    }
    float bias0 = __ldg(b + lane);
    float bias1 = __ldg(b + lane + 32);
    __syncthreads();

    for (int r0 = (blockIdx.x * 8 + wid) * 4; r0 < NN; r0 += gridDim.x * 32) {
        float a0[4], a1[4];
#pragma unroll
        for (int j = 0; j < 4; j++) { a0[j] = bias0; a1[j] = bias1; }
#pragma unroll
        for (int half = 0; half < 2; half++) {
#pragma unroll
            for (int j = 0; j < 4; j++) {
                float2 v = *(const float2*)(x + (size_t)(r0 + j) * NF + half * 64 + lane * 2);
                srow[wid][j][lane * 2] = v.x;
                srow[wid][j][lane * 2 + 1] = v.y;
            }
            __syncwarp();
#pragma unroll
            for (int kb = 0; kb < 16; kb++) {
                float4 wa = *(const float4*)&sWt[half][kb * 256 + lane * 4];
                float4 wb = *(const float4*)&sWt[half][kb * 256 + (lane + 32) * 4];
#pragma unroll
                for (int j = 0; j < 4; j++) {
                    float4 z4 = *(const float4*)&srow[wid][j][kb * 4];
                    a0[j] = fmaf(z4.x, wa.x, a0[j]);
                    a0[j] = fmaf(z4.y, wa.y, a0[j]);
                    a0[j] = fmaf(z4.z, wa.z, a0[j]);
                    a0[j] = fmaf(z4.w, wa.w, a0[j]);
                    a1[j] = fmaf(z4.x, wb.x, a1[j]);
                    a1[j] = fmaf(z4.y, wb.y, a1[j]);
                    a1[j] = fmaf(z4.z, wb.z, a1[j]);
                    a1[j] = fmaf(z4.w, wb.w, a1[j]);
                }
            }
            __syncwarp();
        }
#pragma unroll
        for (int j = 0; j < 4; j++) {
            g_h[(size_t)(r0 + j) * NH + lane] = a0[j];
            g_h[(size_t)(r0 + j) * NH + lane + 32] = a1[j];
        }
    }
}

// ---------------------------------------------------------------------------
// Fused layer: gather (CSR) + (1+eps)*self  ->  2-layer MLP -> g_t + BN stats.
// Warp handles 4 nodes; half-warp gathers one node at a time (2 in parallel).
// smem = 40.5KB -> 5 blocks/SM, gather latency overlaps GEMM issue.
// ---------------------------------------------------------------------------
__global__ void layer_kernel(const float* __restrict__ eps, int l,
                             const float* __restrict__ w1, const float* __restrict__ b1,
                             const float* __restrict__ w2, const float* __restrict__ b2) {
    __shared__ __align__(16) float sW1t[16 * 256];    // 16KB
    __shared__ __align__(16) float sW2t[16 * 256];    // 16KB
    __shared__ __align__(16) float srow[8][4][NH];    // 8KB
    __shared__ float ssum[NH], ssq[NH];
    int tid = threadIdx.x, wid = tid >> 5, lane = tid & 31;
    int half = lane >> 4, lane16 = lane & 15;
    unsigned hmask = 0xFFFFu << (half * 16);

    for (int i = tid; i < NH * NH; i += 256) {
        int k = i >> 6, col = i & 63;
        int idx = (k >> 2) * 256 + col * 4 + (k & 3);
        sW1t[idx] = w1[i];
        sW2t[idx] = w2[i];
    }
    float b1l0 = __ldg(b1 + lane), b1l1 = __ldg(b1 + lane + 32);
    float b2l0 = __ldg(b2 + lane), b2l1 = __ldg(b2 + lane + 32);
    float se = 1.0f + __ldg(eps + l);
    if (tid < NH) { ssum[tid] = 0.0f; ssq[tid] = 0.0f; }
    __syncthreads();

    float cs0 = 0.f, cq0 = 0.f, cs1 = 0.f, cq1 = 0.f;

    for (int r0 = (blockIdx.x * 8 + wid) * 4; r0 < NN; r0 += gridDim.x * 32) {
        // ---- gather phase: 2 nodes in parallel (half-warps), 2 passes ----
#pragma unroll
        for (int p = 0; p < 2; p++) {
            int node = r0 + p * 2 + half;
            float4 acc = *(const float4*)(g_h + (size_t)node * NH + lane16 * 4);
            acc.x *= se; acc.y *= se; acc.z *= se; acc.w *= se;
            int begin = __ldg(&g_off[node]);
            int end   = __ldg(&g_off[node + 1]);
            for (int base = begin; base < end; base += 16) {
                int cnt = min(16, end - base);
                int sidx = (lane16 < cnt) ? __ldg(&g_csr[base + lane16]) : 0;
                int j = 0;
                for (; j + 4 <= cnt; j += 4) {
                    int s0 = __shfl_sync(hmask, sidx, j + 0, 16);
                    int s1 = __shfl_sync(hmask, sidx, j + 1, 16);
                    int s2 = __shfl_sync(hmask, sidx, j + 2, 16);
                    int s3 = __shfl_sync(hmask, sidx, j + 3, 16);
                    float4 v0 = *(const float4*)(g_h + (size_t)s0 * NH + lane16 * 4);
                    float4 v1 = *(const float4*)(g_h + (size_t)s1 * NH + lane16 * 4);
                    float4 v2 = *(const float4*)(g_h + (size_t)s2 * NH + lane16 * 4);
                    float4 v3 = *(const float4*)(g_h + (size_t)s3 * NH + lane16 * 4);
                    acc.x += v0.x; acc.y += v0.y; acc.z += v0.z; acc.w += v0.w;
                    acc.x += v1.x; acc.y += v1.y; acc.z += v1.z; acc.w += v1.w;
                    acc.x += v2.x; acc.y += v2.y; acc.z += v2.z; acc.w += v2.w;
                    acc.x += v3.x; acc.y += v3.y; acc.z += v3.z; acc.w += v3.w;
                }
                for (; j < cnt; j++) {
                    int s0 = __shfl_sync(hmask, sidx, j, 16);
                    float4 v0 = *(const float4*)(g_h + (size_t)s0 * NH + lane16 * 4);
                    acc.x += v0.x; acc.y += v0.y; acc.z += v0.z; acc.w += v0.w;
                }
            }
            *(float4*)&srow[wid][p * 2 + half][lane16 * 4] = acc;
        }
        __syncwarp();

        // ---- GEMM 1: relu(z @ W1 + b1) ----
        float a0[4], a1[4];
#pragma unroll
        for (int j = 0; j < 4; j++) { a0[j] = b1l0; a1[j] = b1l1; }
#pragma unroll
        for (int kb = 0; kb < 16; kb++) {
            float4 wa = *(const float4*)&sW1t[kb * 256 + lane * 4];
            float4 wb = *(const float4*)&sW1t[kb * 256 + (lane + 32) * 4];
#pragma unroll
            for (int j = 0; j < 4; j++) {
                float4 z4 = *(const float4*)&srow[wid][j][kb * 4];
                a0[j] = fmaf(z4.x, wa.x, a0[j]);
                a0[j] = fmaf(z4.y, wa.y, a0[j]);
                a0[j] = fmaf(z4.z, wa.z, a0[j]);
                a0[j] = fmaf(z4.w, wa.w, a0[j]);
                a1[j] = fmaf(z4.x, wb.x, a1[j]);
                a1[j] = fmaf(z4.y, wb.y, a1[j]);
                a1[j] = fmaf(z4.z, wb.z, a1[j]);
                a1[j] = fmaf(z4.w, wb.w, a1[j]);
            }
        }
        __syncwarp();
#pragma unroll
        for (int j = 0; j < 4; j++) {
            srow[wid][j][lane] = fmaxf(a0[j], 0.0f);
            srow[wid][j][lane + 32] = fmaxf(a1[j], 0.0f);
        }
        __syncwarp();

        // ---- GEMM 2: t @ W2 + b2 ----
#pragma unroll
        for (int j = 0; j < 4; j++) { a0[j] = b2l0; a1[j] = b2l1; }
#pragma unroll
        for (int kb = 0; kb < 16; kb++) {
            float4 wa = *(const float4*)&sW2t[kb * 256 + lane * 4];
            float4 wb = *(const float4*)&sW2t[kb * 256 + (lane + 32) * 4];
#pragma unroll
            for (int j = 0; j < 4; j++) {
                float4 z4 = *(const float4*)&srow[wid][j][kb * 4];
                a0[j] = fmaf(z4.x, wa.x, a0[j]);
                a0[j] = fmaf(z4.y, wa.y, a0[j]);
                a0[j] = fmaf(z4.z, wa.z, a0[j]);
                a0[j] = fmaf(z4.w, wa.w, a0[j]);
                a1[j] = fmaf(z4.x, wb.x, a1[j]);
                a1[j] = fmaf(z4.y, wb.y, a1[j]);
                a1[j] = fmaf(z4.z, wb.z, a1[j]);
                a1[j] = fmaf(z4.w, wb.w, a1[j]);
            }
        }
#pragma unroll
        for (int j = 0; j < 4; j++) {
            g_t[(size_t)(r0 + j) * NH + lane] = a0[j];
            g_t[(size_t)(r0 + j) * NH + lane + 32] = a1[j];
            cs0 += a0[j]; cq0 += a0[j] * a0[j];
            cs1 += a1[j]; cq1 += a1[j] * a1[j];
        }
        __syncwarp();
    }
    atomicAdd(&ssum[lane], cs0);
    atomicAdd(&ssum[lane + 32], cs1);
    atomicAdd(&ssq[lane], cq0);
    atomicAdd(&ssq[lane + 32], cq1);
    __syncthreads();
    if (tid < NH) {
        atomicAdd(&g_stats[l][tid], ssum[tid]);
        atomicAdd(&g_stats[l][NH + tid], ssq[tid]);
    }
}

// ---------------------------------------------------------------------------
// BN apply + ReLU: h = relu((t - mean) * rsqrt(var+eps) * gamma + beta)
// ---------------------------------------------------------------------------
__global__ void bn_kernel(const float* __restrict__ gamma,
                          const float* __restrict__ beta, int l) {
    __shared__ float sc[NH], sh[NH];
    int tid = threadIdx.x;
    if (tid < NH) {
        float m = g_stats[l][tid] * (1.0f / NN);
        float v = g_stats[l][NH + tid] * (1.0f / NN) - m * m;
        float inv = rsqrtf(v + 1e-5f);
        float s = inv * __ldg(gamma + tid);
        sc[tid] = s;
        sh[tid] = __ldg(beta + tid) - m * s;
    }
    __syncthreads();
    for (int i = blockIdx.x * blockDim.x + tid; i < NN * NH / 4;
         i += gridDim.x * blockDim.x) {
        int c4 = (i & (NH / 4 - 1)) * 4;
        float4 v = ((const float4*)g_t)[i];
        v.x = fmaxf(v.x * sc[c4 + 0] + sh[c4 + 0], 0.0f);
        v.y = fmaxf(v.y * sc[c4 + 1] + sh[c4 + 1], 0.0f);
        v.z = fmaxf(v.z * sc[c4 + 2] + sh[c4 + 2], 0.0f);
        v.w = fmaxf(v.w * sc[c4 + 3] + sh[c4 + 3], 0.0f);
        ((float4*)g_h)[i] = v;
    }
}

// ---------------------------------------------------------------------------
// Pooling + classifier
// ---------------------------------------------------------------------------
__global__ void pool_kernel(const int* __restrict__ batch) {
    int gid = blockIdx.x * blockDim.x + threadIdx.x;
    int n = gid >> 4;
    if (n >= NN) return;
    int q = (gid & 15) << 2;
    int g = __ldg(batch + n);
    float4 v = *(const float4*)(g_h + (size_t)n * NH + q);
    float* p = g_pool + (size_t)g * NH + q;
    asm volatile("red.global.add.v4.f32 [%0], {%1,%2,%3,%4};"
                 :: "l"(p), "f"(v.x), "f"(v.y), "f"(v.z), "f"(v.w)
                 : "memory");
    if (q == 0) atomicAdd(&g_cnt[g], 1.0f);
}

__global__ void final_kernel(const float* __restrict__ lw,
                             const float* __restrict__ lb,
                             float* __restrict__ out) {
    __shared__ float sp[NH];
    int g = blockIdx.x, tid = threadIdx.x;
    float cnt = fmaxf(g_cnt[g], 1.0f);
    if (tid < NH) sp[tid] = g_pool[g * NH + tid] / cnt;
    __syncthreads();
    if (tid < NC) {
        float acc = __ldg(lb + tid);
        for (int k = 0; k < NH; k++) acc += sp[k] * __ldg(lw + k * NC + tid);
        out[g * NC + tid] = acc;
    }
}

// ---------------------------------------------------------------------------
extern "C" void kernel_launch(void* const* d_in, const int* in_sizes, int n_in,
                              void* d_out, int out_size) {
    const float* x     = (const float*)d_in[0];
    const int*   ei    = (const int*)d_in[1];
    const int*   batch = (const int*)d_in[2];
    const float* enc_w = (const float*)d_in[3];
    const float* enc_b = (const float*)d_in[4];
    const float* eps   = (const float*)d_in[5];
    const float* cw1   = (const float*)d_in[6];
    const float* cb1   = (const float*)d_in[7];
    const float* cw2   = (const float*)d_in[8];
    const float* cb2   = (const float*)d_in[9];
    const float* gam   = (const float*)d_in[10];
    const float* bet   = (const float*)d_in[11];
    const float* lw    = (const float*)d_in[12];
    const float* lb    = (const float*)d_in[13];
    float* out = (float*)d_out;

    zero_misc_kernel<<<SCAN_B, 256>>>();
    hist_kernel<<<(NE + 255) / 256, 256>>>(ei);
    scan_block_kernel<<<SCAN_B, 256>>>();
    scan_top_kernel<<<1, 256>>>();
    scan_apply_kernel<<<SCAN_B, 256>>>();
    fill_kernel<<<(NE + 255) / 256, 256>>>(ei);

    enc_kernel<<<444, 256>>>(x, enc_w, enc_b);
    for (int l = 0; l < NL; l++) {
        layer_kernel<<<444, 256>>>(eps, l,
                                   cw1 + (size_t)l * NH * NH, cb1 + l * NH,
                                   cw2 + (size_t)l * NH * NH, cb2 + l * NH);
        bn_kernel<<<444, 256>>>(gam + l * NH, bet + l * NH, l);
    }
    pool_kernel<<<(NN * 16 + 255) / 256, 256>>>(batch);
    final_kernel<<<NG, 64>>>(lw, lb, out);
}